// round 6
// baseline (speedup 1.0000x reference)
#include <cuda_runtime.h>
#include <cstdint>

typedef unsigned long long ull;
typedef unsigned int uint;

#define D_MODEL 2048
#define N_STATE 256
#define RANK    64
#define LEVELS  8
#define MAX_T   16384

#define E_CTAS 8
#define E_ROWS 8
#define E_SMEM ((N_STATE * RANK + E_ROWS * N_STATE) * (int)sizeof(float))

#define RS 36                      // padded row stride in ull (32 data + 4 pad)
// fused smem: Tsm(64*RS) + WB0(128*RS) + WB1(128*RS) ull
#define F_SMEM ((64 * RS + 2 * 128 * RS) * (int)sizeof(ull))   // 92160

// scratch
__device__ float g_E[RANK * RANK];
__device__ ull g_F1t[RANK * (D_MODEL / 2)];     // [n][kw] (hi bf16x2 | lo<<32)
__device__ ull g_Wt[D_MODEL * (RANK / 2)];      // [n][kw], Wt[n][k]=Wcm[k][n]

// =====================================================================
// helpers
// =====================================================================
__device__ __forceinline__ ull split2(float x0, float x1) {
    uint hh;
    asm("cvt.rn.bf16x2.f32 %0, %1, %2;" : "=r"(hh) : "f"(x1), "f"(x0));
    float h0 = __uint_as_float(hh << 16);
    float h1 = __uint_as_float(hh & 0xffff0000u);
    uint ll;
    asm("cvt.rn.bf16x2.f32 %0, %1, %2;" : "=r"(ll) : "f"(x1 - h1), "f"(x0 - h0));
    return (ull)hh | ((ull)ll << 32);
}

__device__ __forceinline__ void mma16816(float* d, uint a0, uint a1, uint a2, uint a3,
                                         uint b0, uint b1) {
    asm volatile(
        "mma.sync.aligned.m16n8k16.row.col.f32.bf16.bf16.f32 "
        "{%0,%1,%2,%3}, {%4,%5,%6,%7}, {%8,%9}, {%0,%1,%2,%3};"
        : "+f"(d[0]), "+f"(d[1]), "+f"(d[2]), "+f"(d[3])
        : "r"(a0), "r"(a1), "r"(a2), "r"(a3), "r"(b0), "r"(b1));
}

__device__ __forceinline__ uint smem_u32(const void* p) {
    uint a;
    asm("{ .reg .u64 t; cvta.to.shared.u64 t, %1; cvt.u32.u64 %0, t; }" : "=r"(a) : "l"(p));
    return a;
}
__device__ __forceinline__ void cp_async16(uint dst, const void* src) {
    asm volatile("cp.async.cg.shared.global [%0], [%1], 16;" :: "r"(dst), "l"(src));
}
#define CP_COMMIT() asm volatile("cp.async.commit_group;" ::: "memory")
#define CP_WAIT0()  asm volatile("cp.async.wait_group 0;" ::: "memory")

// =====================================================================
// Kernel 0: E = Wbs @ Butterfly @ Wcr   (64x64)
// =====================================================================
__global__ __launch_bounds__(256) void compute_E_kernel(const float* __restrict__ A_factors,
                                                        const float* __restrict__ Wbs,
                                                        const float* __restrict__ Wcr) {
    extern __shared__ float esm[];
    float* Wcr_s = esm;
    float* G     = esm + N_STATE * RANK;
    __shared__ float Af[LEVELS * 4];
    const int tid = threadIdx.x;
    const int r0 = blockIdx.x * E_ROWS;
    if (tid < LEVELS * 4) Af[tid] = A_factors[tid];

    for (int i = tid; i < N_STATE * RANK / 4; i += 256)
        ((float4*)Wcr_s)[i] = ((const float4*)Wcr)[i];
    for (int i = tid; i < E_ROWS * N_STATE / 4; i += 256)
        ((float4*)G)[i] = ((const float4*)(Wbs + (size_t)r0 * N_STATE))[i];
    __syncthreads();

#pragma unroll
    for (int lvl = 0; lvl < LEVELS; lvl++) {
        const int stride = 128 >> lvl;
        const float a00 = Af[lvl * 4 + 0], a01 = Af[lvl * 4 + 1];
        const float a10 = Af[lvl * 4 + 2], a11 = Af[lvl * 4 + 3];
#pragma unroll
        for (int p = tid; p < E_ROWS * 128; p += 256) {
            int r  = p >> 7;
            int pi = p & 127;
            int low = pi & (stride - 1);
            int n0  = ((pi - low) << 1) | low;
            int n1  = n0 + stride;
            float x0 = G[r * N_STATE + n0];
            float x1 = G[r * N_STATE + n1];
            G[r * N_STATE + n0] = x0 * a00 + x1 * a10;
            G[r * N_STATE + n1] = x0 * a01 + x1 * a11;
        }
        __syncthreads();
    }

    for (int o = tid; o < E_ROWS * RANK; o += 256) {
        int r = o >> 6, j = o & 63;
        float acc = 0.f;
#pragma unroll 8
        for (int n = 0; n < N_STATE; n++)
            acc += G[r * N_STATE + n] * Wcr_s[n * RANK + j];
        g_E[(r0 + r) * RANK + j] = acc;
    }
}

// =====================================================================
// Kernel 1: F1t[n][kw] = hi/lo split of (Wbr @ E)^T.
// =====================================================================
__global__ __launch_bounds__(64) void compute_F1t_kernel(const float* __restrict__ Wbr) {
    __shared__ float Ws[64 * 64];
    __shared__ float Es[64 * 64];
    __shared__ float F[64 * 64];
    const int tid = threadIdx.x;
    const int k0 = blockIdx.x * 64;
    for (int i = tid; i < 64 * 16; i += 64)
        ((float4*)Ws)[i] = ((const float4*)(Wbr + (size_t)k0 * 64))[i];
    for (int i = tid; i < 64 * 16; i += 64)
        ((float4*)Es)[i] = ((const float4*)g_E)[i];
    __syncthreads();
#pragma unroll 4
    for (int n = 0; n < 64; n++) {
        float acc = 0.f;
#pragma unroll
        for (int r = 0; r < 64; r++)
            acc += Ws[tid * 64 + r] * Es[r * 64 + n];
        F[tid * 64 + n] = acc;
    }
    __syncthreads();
#pragma unroll 4
    for (int kw = 0; kw < 32; kw++) {
        g_F1t[tid * (D_MODEL / 2) + blockIdx.x * 32 + kw] =
            split2(F[(2 * kw) * 64 + tid], F[(2 * kw + 1) * 64 + tid]);
    }
}

// =====================================================================
// Kernel 1b: Wt[n][kw] = hi/lo split of Wcm^T.
// =====================================================================
__global__ __launch_bounds__(256) void compute_Wcmt_kernel(const float* __restrict__ Wcm) {
    __shared__ float S[64 * 65];
    const int tid = threadIdx.x;
    const int n0 = blockIdx.x * 64;
#pragma unroll
    for (int it = 0; it < 16; it++) {
        int idx = it * 256 + tid;
        int k = idx >> 6, nn = idx & 63;
        S[nn * 65 + k] = Wcm[(size_t)k * D_MODEL + n0 + nn];
    }
    __syncthreads();
#pragma unroll
    for (int it = 0; it < 8; it++) {
        int idx = it * 256 + tid;
        int nn = idx >> 5, kw = idx & 31;
        g_Wt[(size_t)(n0 + nn) * 32 + kw] = split2(S[nn * 65 + 2 * kw], S[nn * 65 + 2 * kw + 1]);
    }
}

// =====================================================================
// FUSED kernel: per CTA rows [row0, row0+64)
//   phase 1: t_tile = u_rows @ F1 (K=2048, 32 chunks, bf16 hi/lo MMA)
//   phase 2: out_rows = t_tile @ Wcm + D*u (16 col-chunks of 128,
//            cp.async double-buffered Wt, u re-read hits L2)
// =====================================================================
__global__ __launch_bounds__(256, 2) void fused_mma(const float* __restrict__ u,
                                                    const float* __restrict__ Dv,
                                                    float* __restrict__ out) {
    extern __shared__ ull dsm[];
    ull* Tsm = dsm;                      // [64 * RS]
    ull* WB[2] = { dsm + 64 * RS, dsm + 64 * RS + 128 * RS };

    const int tid = threadIdx.x;
    const int lane = tid & 31;
    const int w = tid >> 5;
    const int g = lane >> 2;
    const int c = lane & 3;
    const int m0 = (w & 3) * 16;
    const int wn = w >> 2;
    const size_t row0 = (size_t)blockIdx.x * 64;

    // ================= phase 1 =================
    const int n0 = wn * 32;
    const int arow = tid >> 2;
    const int akq  = tid & 3;

    float acc1[4][4];
#pragma unroll
    for (int i = 0; i < 4; i++)
#pragma unroll
        for (int j = 0; j < 4; j++) acc1[i][j] = 0.f;

    float4 pu[4];
    ull pb[8];
    {
        const float* up = u + (row0 + arow) * D_MODEL + akq * 16;
#pragma unroll
        for (int j = 0; j < 4; j++) pu[j] = *(const float4*)(up + j * 4);
#pragma unroll
        for (int i = 0; i < 8; i++) {
            int idx = tid + i * 256;
            pb[i] = g_F1t[(idx >> 5) * (D_MODEL / 2) + (idx & 31)];
        }
    }

    for (int ch = 0; ch < 32; ch++) {
        ull* As = WB[ch & 1];            // staging set: A at 0, B at +64*RS
        ull* Bs = WB[ch & 1] + 64 * RS;
        {
            const int kwb = akq * 8;
#pragma unroll
            for (int j = 0; j < 4; j++) {
                As[arow * RS + kwb + 2 * j]     = split2(pu[j].x, pu[j].y);
                As[arow * RS + kwb + 2 * j + 1] = split2(pu[j].z, pu[j].w);
            }
#pragma unroll
            for (int i = 0; i < 8; i++) {
                int idx = tid + i * 256;
                Bs[(idx >> 5) * RS + (idx & 31)] = pb[i];
            }
        }
        __syncthreads();
        if (ch + 1 < 32) {
            const float* up = u + (row0 + arow) * D_MODEL + (ch + 1) * 64 + akq * 16;
#pragma unroll
            for (int j = 0; j < 4; j++) pu[j] = *(const float4*)(up + j * 4);
#pragma unroll
            for (int i = 0; i < 8; i++) {
                int idx = tid + i * 256;
                pb[i] = g_F1t[(idx >> 5) * (D_MODEL / 2) + (ch + 1) * 32 + (idx & 31)];
            }
        }
#pragma unroll
        for (int ks = 0; ks < 4; ks++) {
            const int kwb = ks * 8;
            ull a0 = As[(m0 + g) * RS + kwb + c];
            ull a1 = As[(m0 + g + 8) * RS + kwb + c];
            ull a2 = As[(m0 + g) * RS + kwb + 4 + c];
            ull a3 = As[(m0 + g + 8) * RS + kwb + 4 + c];
            uint ah0 = (uint)a0, al0 = (uint)(a0 >> 32);
            uint ah1 = (uint)a1, al1 = (uint)(a1 >> 32);
            uint ah2 = (uint)a2, al2 = (uint)(a2 >> 32);
            uint ah3 = (uint)a3, al3 = (uint)(a3 >> 32);
            ull b0[4], b1[4];
#pragma unroll
            for (int nt = 0; nt < 4; nt++) {
                b0[nt] = Bs[(n0 + nt * 8 + g) * RS + kwb + c];
                b1[nt] = Bs[(n0 + nt * 8 + g) * RS + kwb + 4 + c];
            }
            // term-interleaved: same-acc deps are >=4 issues apart
#pragma unroll
            for (int nt = 0; nt < 4; nt++)
                mma16816(acc1[nt], ah0, ah1, ah2, ah3, (uint)b0[nt], (uint)b1[nt]);
#pragma unroll
            for (int nt = 0; nt < 4; nt++)
                mma16816(acc1[nt], ah0, ah1, ah2, ah3, (uint)(b0[nt] >> 32), (uint)(b1[nt] >> 32));
#pragma unroll
            for (int nt = 0; nt < 4; nt++)
                mma16816(acc1[nt], al0, al1, al2, al3, (uint)b0[nt], (uint)b1[nt]);
        }
        __syncthreads();   // all warps done with this staging set before overwrite
    }

    // ================= phase boundary =================
    // issue first Wt chunk (overlaps with t-tile split/store)
    const uint wb_addr[2] = { smem_u32(WB[0]), smem_u32(WB[1]) };
    {
#pragma unroll
        for (int j = 0; j < 8; j++) {
            int idx = tid + j * 256;
            int r = idx >> 4, seg = idx & 15;
            cp_async16(wb_addr[0] + (uint)(r * RS + seg * 2) * 8,
                       &g_Wt[(size_t)r * 32 + seg * 2]);
        }
        CP_COMMIT();
    }
    // t tile -> Tsm (hi/lo split, fragment layout)
#pragma unroll
    for (int nt = 0; nt < 4; nt++) {
        int kw = (n0 >> 1) + nt * 4 + c;
        int r = m0 + g;
        Tsm[r * RS + kw]       = split2(acc1[nt][0], acc1[nt][1]);
        Tsm[(r + 8) * RS + kw] = split2(acc1[nt][2], acc1[nt][3]);
    }
    __syncthreads();

    // ================= phase 2 =================
    const int n0b = wn * 64;   // warp covers 64 of 128 chunk cols

    // preload A fragments (t tile) once: 4 ks x (hi,lo)
    uint ah[4][4], al[4][4];
#pragma unroll
    for (int ks = 0; ks < 4; ks++) {
        const int kwb = ks * 8;
        ull a0 = Tsm[(m0 + g) * RS + kwb + c];
        ull a1 = Tsm[(m0 + g + 8) * RS + kwb + c];
        ull a2 = Tsm[(m0 + g) * RS + kwb + 4 + c];
        ull a3 = Tsm[(m0 + g + 8) * RS + kwb + 4 + c];
        ah[ks][0] = (uint)a0; al[ks][0] = (uint)(a0 >> 32);
        ah[ks][1] = (uint)a1; al[ks][1] = (uint)(a1 >> 32);
        ah[ks][2] = (uint)a2; al[ks][2] = (uint)(a2 >> 32);
        ah[ks][3] = (uint)a3; al[ks][3] = (uint)(a3 >> 32);
    }

    for (int cc = 0; cc < 16; cc++) {
        CP_WAIT0();
        __syncthreads();
        if (cc + 1 < 16) {
            const size_t nb = (size_t)(cc + 1) * 128;
            const uint dst = wb_addr[(cc + 1) & 1];
#pragma unroll
            for (int j = 0; j < 8; j++) {
                int idx = tid + j * 256;
                int r = idx >> 4, seg = idx & 15;
                cp_async16(dst + (uint)(r * RS + seg * 2) * 8,
                           &g_Wt[(nb + r) * 32 + seg * 2]);
            }
            CP_COMMIT();
        }
        const ull* Bs = WB[cc & 1];

        float acc2[8][4];
#pragma unroll
        for (int a = 0; a < 8; a++)
#pragma unroll
            for (int d = 0; d < 4; d++) acc2[a][d] = 0.f;

#pragma unroll
        for (int ks = 0; ks < 4; ks++) {
            const int kwb = ks * 8;
            ull b0[8], b1[8];
#pragma unroll
            for (int nt = 0; nt < 8; nt++) {
                b0[nt] = Bs[(n0b + nt * 8 + g) * RS + kwb + c];
                b1[nt] = Bs[(n0b + nt * 8 + g) * RS + kwb + 4 + c];
            }
#pragma unroll
            for (int nt = 0; nt < 8; nt++)
                mma16816(acc2[nt], ah[ks][0], ah[ks][1], ah[ks][2], ah[ks][3],
                         (uint)b0[nt], (uint)b1[nt]);
#pragma unroll
            for (int nt = 0; nt < 8; nt++)
                mma16816(acc2[nt], ah[ks][0], ah[ks][1], ah[ks][2], ah[ks][3],
                         (uint)(b0[nt] >> 32), (uint)(b1[nt] >> 32));
#pragma unroll
            for (int nt = 0; nt < 8; nt++)
                mma16816(acc2[nt], al[ks][0], al[ks][1], al[ks][2], al[ks][3],
                         (uint)b0[nt], (uint)b1[nt]);
        }

        // epilogue: out = acc + D*u (u rows are L2-hot from phase 1)
        const int colw = cc * 128 + n0b;
#pragma unroll
        for (int nt = 0; nt < 8; nt++) {
            int col = colw + nt * 8 + c * 2;
            float2 dv = __ldg((const float2*)(Dv + col));
            size_t r0g = (row0 + m0 + g) * D_MODEL + col;
            size_t r1g = r0g + 8 * D_MODEL;
            float2 u0 = __ldg((const float2*)(u + r0g));
            float2 u1 = __ldg((const float2*)(u + r1g));
            *(float2*)(out + r0g) = make_float2(acc2[nt][0] + dv.x * u0.x,
                                                acc2[nt][1] + dv.y * u0.y);
            *(float2*)(out + r1g) = make_float2(acc2[nt][2] + dv.x * u1.x,
                                                acc2[nt][3] + dv.y * u1.y);
        }
    }
}

extern "C" void kernel_launch(void* const* d_in, const int* in_sizes, int n_in,
                              void* d_out, int out_size) {
    const float* u   = (const float*)d_in[0];
    const float* Af  = (const float*)d_in[1];
    const float* Wbr = (const float*)d_in[2];
    const float* Wbs = (const float*)d_in[3];
    const float* Wcr = (const float*)d_in[4];
    const float* Wcm = (const float*)d_in[5];
    const float* Dv  = (const float*)d_in[6];
    float* out = (float*)d_out;

    const int T = in_sizes[0] / D_MODEL;   // 16384

    cudaFuncSetAttribute(compute_E_kernel, cudaFuncAttributeMaxDynamicSharedMemorySize, E_SMEM);
    cudaFuncSetAttribute(fused_mma, cudaFuncAttributeMaxDynamicSharedMemorySize, F_SMEM);

    compute_E_kernel<<<E_CTAS, 256, E_SMEM>>>(Af, Wbs, Wcr);
    compute_F1t_kernel<<<32, 64>>>(Wbr);
    compute_Wcmt_kernel<<<32, 256>>>(Wcm);
    fused_mma<<<T / 64, 256, F_SMEM>>>(u, Dv, out);
}

// round 7
// speedup vs baseline: 1.0388x; 1.0388x over previous
#include <cuda_runtime.h>
#include <cstdint>

typedef unsigned long long ull;
typedef unsigned int uint;

#define D_MODEL 2048
#define N_STATE 256
#define RANK    64
#define LEVELS  8
#define MAX_T   16384

#define E_CTAS 8
#define E_ROWS 8
#define E_SMEM ((N_STATE * RANK + E_ROWS * N_STATE) * (int)sizeof(float))

#define RSB 36    // B smem row stride in ull (32 data + 4 pad)

// scratch
__device__ float g_E[RANK * RANK];
__device__ ull g_F1t[RANK * (D_MODEL / 2)];     // [n][kw] (hi bf16x2 | lo<<32)
__device__ ull g_Wt[D_MODEL * (RANK / 2)];      // [n][kw], Wt[n][k]=Wcm[k][n]
__device__ ull g_t[MAX_T * (RANK / 2)];         // [row][kw]

// =====================================================================
// helpers
// =====================================================================
__device__ __forceinline__ ull split2(float x0, float x1) {
    uint hh;
    asm("cvt.rn.bf16x2.f32 %0, %1, %2;" : "=r"(hh) : "f"(x1), "f"(x0));
    float h0 = __uint_as_float(hh << 16);
    float h1 = __uint_as_float(hh & 0xffff0000u);
    uint ll;
    asm("cvt.rn.bf16x2.f32 %0, %1, %2;" : "=r"(ll) : "f"(x1 - h1), "f"(x0 - h0));
    return (ull)hh | ((ull)ll << 32);
}

__device__ __forceinline__ void mma16816(float* d, uint a0, uint a1, uint a2, uint a3,
                                         uint b0, uint b1) {
    asm volatile(
        "mma.sync.aligned.m16n8k16.row.col.f32.bf16.bf16.f32 "
        "{%0,%1,%2,%3}, {%4,%5,%6,%7}, {%8,%9}, {%0,%1,%2,%3};"
        : "+f"(d[0]), "+f"(d[1]), "+f"(d[2]), "+f"(d[3])
        : "r"(a0), "r"(a1), "r"(a2), "r"(a3), "r"(b0), "r"(b1));
}

__device__ __forceinline__ uint smem_u32(const void* p) {
    uint a;
    asm("{ .reg .u64 t; cvta.to.shared.u64 t, %1; cvt.u32.u64 %0, t; }" : "=r"(a) : "l"(p));
    return a;
}
__device__ __forceinline__ void cp_async16(uint dst, const void* src) {
    asm volatile("cp.async.cg.shared.global [%0], [%1], 16;" :: "r"(dst), "l"(src));
}
#define CP_COMMIT() asm volatile("cp.async.commit_group;" ::: "memory")
#define CP_WAIT0()  asm volatile("cp.async.wait_group 0;" ::: "memory")

// =====================================================================
// Kernel 0: E = Wbs @ Butterfly @ Wcr   (64x64)
// =====================================================================
__global__ __launch_bounds__(256) void compute_E_kernel(const float* __restrict__ A_factors,
                                                        const float* __restrict__ Wbs,
                                                        const float* __restrict__ Wcr) {
    extern __shared__ float esm[];
    float* Wcr_s = esm;
    float* G     = esm + N_STATE * RANK;
    __shared__ float Af[LEVELS * 4];
    const int tid = threadIdx.x;
    const int r0 = blockIdx.x * E_ROWS;
    if (tid < LEVELS * 4) Af[tid] = A_factors[tid];

    for (int i = tid; i < N_STATE * RANK / 4; i += 256)
        ((float4*)Wcr_s)[i] = ((const float4*)Wcr)[i];
    for (int i = tid; i < E_ROWS * N_STATE / 4; i += 256)
        ((float4*)G)[i] = ((const float4*)(Wbs + (size_t)r0 * N_STATE))[i];
    __syncthreads();

#pragma unroll
    for (int lvl = 0; lvl < LEVELS; lvl++) {
        const int stride = 128 >> lvl;
        const float a00 = Af[lvl * 4 + 0], a01 = Af[lvl * 4 + 1];
        const float a10 = Af[lvl * 4 + 2], a11 = Af[lvl * 4 + 3];
#pragma unroll
        for (int p = tid; p < E_ROWS * 128; p += 256) {
            int r  = p >> 7;
            int pi = p & 127;
            int low = pi & (stride - 1);
            int n0  = ((pi - low) << 1) | low;
            int n1  = n0 + stride;
            float x0 = G[r * N_STATE + n0];
            float x1 = G[r * N_STATE + n1];
            G[r * N_STATE + n0] = x0 * a00 + x1 * a10;
            G[r * N_STATE + n1] = x0 * a01 + x1 * a11;
        }
        __syncthreads();
    }

    for (int o = tid; o < E_ROWS * RANK; o += 256) {
        int r = o >> 6, j = o & 63;
        float acc = 0.f;
#pragma unroll 8
        for (int n = 0; n < N_STATE; n++)
            acc += G[r * N_STATE + n] * Wcr_s[n * RANK + j];
        g_E[(r0 + r) * RANK + j] = acc;
    }
}

// =====================================================================
// Kernel 1: F1t[n][kw] = hi/lo split of (Wbr @ E)^T.
// 32 blocks x 256 threads. Ws staged TRANSPOSED (bank-conflict fix).
// =====================================================================
__global__ __launch_bounds__(256) void compute_F1t_kernel(const float* __restrict__ Wbr) {
    __shared__ float Wst[64 * 65];   // [r][k_local]
    __shared__ float Es[64 * 64];
    __shared__ float Fs[64 * 65];    // [n][k_local]
    const int tid = threadIdx.x;
    const int k0 = blockIdx.x * 64;

#pragma unroll
    for (int i = 0; i < 16; i++) {
        int idx = tid + i * 256;
        int k = idx >> 6, r = idx & 63;
        Wst[r * 65 + k] = Wbr[(size_t)(k0 + k) * 64 + r];
    }
#pragma unroll
    for (int i = 0; i < 4; i++)
        ((float4*)Es)[tid + i * 256] = ((const float4*)g_E)[tid + i * 256];
    __syncthreads();

    const int k = tid & 63, nq = tid >> 6;
#pragma unroll
    for (int nn = 0; nn < 16; nn++) {
        int n = nq * 16 + nn;
        float acc = 0.f;
#pragma unroll 8
        for (int r = 0; r < 64; r++)
            acc += Wst[r * 65 + k] * Es[r * 64 + n];
        Fs[n * 65 + k] = acc;
    }
    __syncthreads();

#pragma unroll
    for (int i = 0; i < 8; i++) {
        int idx = tid + i * 256;
        int n = idx >> 5, kw = idx & 31;
        g_F1t[(size_t)n * (D_MODEL / 2) + blockIdx.x * 32 + kw] =
            split2(Fs[n * 65 + 2 * kw], Fs[n * 65 + 2 * kw + 1]);
    }
}

// =====================================================================
// Kernel 1b: Wt[n][kw] = hi/lo split of Wcm^T.
// =====================================================================
__global__ __launch_bounds__(256) void compute_Wcmt_kernel(const float* __restrict__ Wcm) {
    __shared__ float S[64 * 65];
    const int tid = threadIdx.x;
    const int n0 = blockIdx.x * 64;
#pragma unroll
    for (int it = 0; it < 16; it++) {
        int idx = it * 256 + tid;
        int k = idx >> 6, nn = idx & 63;
        S[nn * 65 + k] = Wcm[(size_t)k * D_MODEL + n0 + nn];
    }
    __syncthreads();
#pragma unroll
    for (int it = 0; it < 8; it++) {
        int idx = it * 256 + tid;
        int nn = idx >> 5, kw = idx & 31;
        g_Wt[(size_t)(n0 + nn) * 32 + kw] = split2(S[nn * 65 + 2 * kw], S[nn * 65 + 2 * kw + 1]);
    }
}

// =====================================================================
// Kernel 2: GEMM1: t = u @ F1.  M=64/CTA, N=64, K=2048 (32 chunks).
// A: direct global->fragment loads + in-reg hi/lo convert (no staging).
// B: cp.async double-buffered smem (16KB/chunk). One sync per chunk.
// =====================================================================
__global__ __launch_bounds__(256) void gemm1_mma(const float* __restrict__ u) {
    __shared__ ull Bsm[2][64 * RSB];
    const int tid = threadIdx.x;
    const int lane = tid & 31;
    const int w = tid >> 5;
    const int g = lane >> 2, c = lane & 3;
    const int m0 = (w & 3) * 16;
    const int n0 = (w >> 2) * 32;
    const size_t row0 = (size_t)blockIdx.x * 64;

    const float* uA0 = u + (row0 + m0 + g) * D_MODEL + c * 2;
    const float* uA1 = uA0 + 8 * D_MODEL;

    float acc[4][4];
#pragma unroll
    for (int i = 0; i < 4; i++)
#pragma unroll
        for (int j = 0; j < 4; j++) acc[i][j] = 0.f;

    float2 pa[16];
    const uint bsm0 = smem_u32(&Bsm[0][0]);
    const uint bsm1 = smem_u32(&Bsm[1][0]);

    // preload A chunk 0
#pragma unroll
    for (int ks = 0; ks < 4; ks++) {
        pa[ks * 4 + 0] = *(const float2*)(uA0 + ks * 16);
        pa[ks * 4 + 1] = *(const float2*)(uA1 + ks * 16);
        pa[ks * 4 + 2] = *(const float2*)(uA0 + ks * 16 + 8);
        pa[ks * 4 + 3] = *(const float2*)(uA1 + ks * 16 + 8);
    }
    // B chunk 0 via cp.async
    {
#pragma unroll
        for (int j = 0; j < 4; j++) {
            int idx = tid + j * 256;
            int n = idx >> 4, seg = idx & 15;
            cp_async16(bsm0 + (uint)(n * RSB + seg * 2) * 8,
                       &g_F1t[(size_t)n * (D_MODEL / 2) + seg * 2]);
        }
        CP_COMMIT();
    }

    for (int ch = 0; ch < 32; ch++) {
        CP_WAIT0();
        __syncthreads();
        if (ch + 1 < 32) {
            const uint dst = (ch & 1) ? bsm0 : bsm1;
            const int kb = (ch + 1) * 32;
#pragma unroll
            for (int j = 0; j < 4; j++) {
                int idx = tid + j * 256;
                int n = idx >> 4, seg = idx & 15;
                cp_async16(dst + (uint)(n * RSB + seg * 2) * 8,
                           &g_F1t[(size_t)n * (D_MODEL / 2) + kb + seg * 2]);
            }
            CP_COMMIT();
        }
        // convert current A to fragments
        ull afr[16];
#pragma unroll
        for (int i = 0; i < 16; i++) afr[i] = split2(pa[i].x, pa[i].y);
        // prefetch next A
        if (ch + 1 < 32) {
            const int kb = (ch + 1) * 64;
#pragma unroll
            for (int ks = 0; ks < 4; ks++) {
                pa[ks * 4 + 0] = *(const float2*)(uA0 + kb + ks * 16);
                pa[ks * 4 + 1] = *(const float2*)(uA1 + kb + ks * 16);
                pa[ks * 4 + 2] = *(const float2*)(uA0 + kb + ks * 16 + 8);
                pa[ks * 4 + 3] = *(const float2*)(uA1 + kb + ks * 16 + 8);
            }
        }
        const ull* Bs = Bsm[ch & 1];
#pragma unroll
        for (int ks = 0; ks < 4; ks++) {
            uint ah0 = (uint)afr[ks * 4 + 0], al0 = (uint)(afr[ks * 4 + 0] >> 32);
            uint ah1 = (uint)afr[ks * 4 + 1], al1 = (uint)(afr[ks * 4 + 1] >> 32);
            uint ah2 = (uint)afr[ks * 4 + 2], al2 = (uint)(afr[ks * 4 + 2] >> 32);
            uint ah3 = (uint)afr[ks * 4 + 3], al3 = (uint)(afr[ks * 4 + 3] >> 32);
            ull b0[4], b1[4];
#pragma unroll
            for (int nt = 0; nt < 4; nt++) {
                b0[nt] = Bs[(n0 + nt * 8 + g) * RSB + ks * 8 + c];
                b1[nt] = Bs[(n0 + nt * 8 + g) * RSB + ks * 8 + 4 + c];
            }
#pragma unroll
            for (int nt = 0; nt < 4; nt++)
                mma16816(acc[nt], ah0, ah1, ah2, ah3, (uint)b0[nt], (uint)b1[nt]);
#pragma unroll
            for (int nt = 0; nt < 4; nt++)
                mma16816(acc[nt], ah0, ah1, ah2, ah3,
                         (uint)(b0[nt] >> 32), (uint)(b1[nt] >> 32));
#pragma unroll
            for (int nt = 0; nt < 4; nt++)
                mma16816(acc[nt], al0, al1, al2, al3, (uint)b0[nt], (uint)b1[nt]);
        }
    }

    // epilogue: t as hi/lo bf16 word pairs (fragment-compatible layout)
#pragma unroll
    for (int nt = 0; nt < 4; nt++) {
        int kw = (n0 >> 1) + nt * 4 + c;
        size_t r = row0 + m0 + g;
        g_t[r * 32 + kw]       = split2(acc[nt][0], acc[nt][1]);
        g_t[(r + 8) * 32 + kw] = split2(acc[nt][2], acc[nt][3]);
    }
}

// =====================================================================
// Kernel 3: GEMM2: out = t @ Wcm + D*u.  Tile 64x128, grid 4096.
// Fully smem-free: A frags direct from g_t, B frags direct from
// L2-hot g_Wt. No syncs. ks-outer MMA interleave (deps 8 apart).
// =====================================================================
__global__ __launch_bounds__(256) void gemm2_mma(const float* __restrict__ u,
                                                 const float* __restrict__ Dv,
                                                 float* __restrict__ out) {
    const int tid = threadIdx.x;
    const int lane = tid & 31;
    const int w = tid >> 5;
    const int g = lane >> 2, c = lane & 3;
    const int m0 = (w & 3) * 16;
    const int n0b = (w >> 2) * 64;
    const int ct = blockIdx.x & 15;
    const int rt = blockIdx.x >> 4;
    const size_t row0 = (size_t)rt * 64;
    const int col0 = ct * 128;

    // A fragments (t tile rows)
    ull afr[16];
    {
        const ull* tA0 = g_t + (row0 + m0 + g) * 32;
        const ull* tA1 = tA0 + 8 * 32;
#pragma unroll
        for (int ks = 0; ks < 4; ks++) {
            afr[ks * 4 + 0] = tA0[ks * 8 + c];
            afr[ks * 4 + 1] = tA1[ks * 8 + c];
            afr[ks * 4 + 2] = tA0[ks * 8 + 4 + c];
            afr[ks * 4 + 3] = tA1[ks * 8 + 4 + c];
        }
    }

    float acc[8][4];
#pragma unroll
    for (int i = 0; i < 8; i++)
#pragma unroll
        for (int j = 0; j < 4; j++) acc[i][j] = 0.f;

#pragma unroll
    for (int ks = 0; ks < 4; ks++) {
        uint ah0 = (uint)afr[ks * 4 + 0], al0 = (uint)(afr[ks * 4 + 0] >> 32);
        uint ah1 = (uint)afr[ks * 4 + 1], al1 = (uint)(afr[ks * 4 + 1] >> 32);
        uint ah2 = (uint)afr[ks * 4 + 2], al2 = (uint)(afr[ks * 4 + 2] >> 32);
        uint ah3 = (uint)afr[ks * 4 + 3], al3 = (uint)(afr[ks * 4 + 3] >> 32);
        ull b0[8], b1[8];
#pragma unroll
        for (int nt = 0; nt < 8; nt++) {
            const ull* Bp = g_Wt + (size_t)(col0 + n0b + nt * 8 + g) * 32 + ks * 8;
            b0[nt] = Bp[c];
            b1[nt] = Bp[4 + c];
        }
#pragma unroll
        for (int nt = 0; nt < 8; nt++)
            mma16816(acc[nt], ah0, ah1, ah2, ah3, (uint)b0[nt], (uint)b1[nt]);
#pragma unroll
        for (int nt = 0; nt < 8; nt++)
            mma16816(acc[nt], ah0, ah1, ah2, ah3,
                     (uint)(b0[nt] >> 32), (uint)(b1[nt] >> 32));
#pragma unroll
        for (int nt = 0; nt < 8; nt++)
            mma16816(acc[nt], al0, al1, al2, al3, (uint)b0[nt], (uint)b1[nt]);
    }

    // epilogue: out = acc + D*u (direct float2 stores)
#pragma unroll
    for (int nt = 0; nt < 8; nt++) {
        int col = col0 + n0b + nt * 8 + c * 2;
        float2 dv = __ldg((const float2*)(Dv + col));
        size_t r0g = (row0 + m0 + g) * D_MODEL + col;
        size_t r1g = r0g + 8 * D_MODEL;
        float2 u0 = __ldg((const float2*)(u + r0g));
        float2 u1 = __ldg((const float2*)(u + r1g));
        *(float2*)(out + r0g) = make_float2(acc[nt][0] + dv.x * u0.x,
                                            acc[nt][1] + dv.y * u0.y);
        *(float2*)(out + r1g) = make_float2(acc[nt][2] + dv.x * u1.x,
                                            acc[nt][3] + dv.y * u1.y);
    }
}

extern "C" void kernel_launch(void* const* d_in, const int* in_sizes, int n_in,
                              void* d_out, int out_size) {
    const float* u   = (const float*)d_in[0];
    const float* Af  = (const float*)d_in[1];
    const float* Wbr = (const float*)d_in[2];
    const float* Wbs = (const float*)d_in[3];
    const float* Wcr = (const float*)d_in[4];
    const float* Wcm = (const float*)d_in[5];
    const float* Dv  = (const float*)d_in[6];
    float* out = (float*)d_out;

    const int T = in_sizes[0] / D_MODEL;   // 16384

    cudaFuncSetAttribute(compute_E_kernel, cudaFuncAttributeMaxDynamicSharedMemorySize, E_SMEM);

    compute_E_kernel<<<E_CTAS, 256, E_SMEM>>>(Af, Wbs, Wcr);
    compute_F1t_kernel<<<32, 256>>>(Wbr);
    compute_Wcmt_kernel<<<32, 256>>>(Wcm);
    gemm1_mma<<<T / 64, 256>>>(u);
    gemm2_mma<<<(T / 64) * (D_MODEL / 128), 256>>>(u, Dv, out);
}

// round 8
// speedup vs baseline: 1.3774x; 1.3259x over previous
#include <cuda_runtime.h>
#include <cstdint>

typedef unsigned long long ull;
typedef unsigned int uint;

#define D_MODEL 2048
#define N_STATE 256
#define RANK    64
#define LEVELS  8
#define MAX_T   16384

#define E_CTAS 8
#define E_ROWS 8
#define E_SMEM ((N_STATE * RANK + E_ROWS * N_STATE) * (int)sizeof(float))

#define RSB 36         // B smem row stride in ull (32 data + 4 pad)
#define UST 68         // u smem row stride in floats (64 data + 4 pad, 16B-multiple)

// ---- gemm1 pipeline ----
#define NSTAGE 3
#define U_STAGE_B (64 * UST * 4)              // 17408
#define B_STAGE_B (64 * RSB * 8)              // 18432
#define STAGE_B   (U_STAGE_B + B_STAGE_B)     // 35840
#define G1_SMEM   (NSTAGE * STAGE_B)          // 107520

// ---- gemm2 smem ----
#define G2A_B (64 * RSB * 8)                  // 18432
#define G2B_B (128 * RSB * 8)                 // 36864
#define G2_SMEM (G2A_B + G2B_B)               // 55296

// scratch
__device__ float g_E[RANK * RANK];
__device__ ull g_F1t[RANK * (D_MODEL / 2)];     // [n][kw] (hi bf16x2 | lo<<32)
__device__ ull g_Wt[D_MODEL * (RANK / 2)];      // [n][kw], Wt[n][k]=Wcm[k][n]
__device__ ull g_t[MAX_T * (RANK / 2)];         // [row][kw]

// =====================================================================
// helpers
// =====================================================================
__device__ __forceinline__ ull split2(float x0, float x1) {
    uint hh;
    asm("cvt.rn.bf16x2.f32 %0, %1, %2;" : "=r"(hh) : "f"(x1), "f"(x0));
    float h0 = __uint_as_float(hh << 16);
    float h1 = __uint_as_float(hh & 0xffff0000u);
    uint ll;
    asm("cvt.rn.bf16x2.f32 %0, %1, %2;" : "=r"(ll) : "f"(x1 - h1), "f"(x0 - h0));
    return (ull)hh | ((ull)ll << 32);
}

__device__ __forceinline__ void mma16816(float* d, uint a0, uint a1, uint a2, uint a3,
                                         uint b0, uint b1) {
    asm volatile(
        "mma.sync.aligned.m16n8k16.row.col.f32.bf16.bf16.f32 "
        "{%0,%1,%2,%3}, {%4,%5,%6,%7}, {%8,%9}, {%0,%1,%2,%3};"
        : "+f"(d[0]), "+f"(d[1]), "+f"(d[2]), "+f"(d[3])
        : "r"(a0), "r"(a1), "r"(a2), "r"(a3), "r"(b0), "r"(b1));
}

__device__ __forceinline__ uint smem_u32(const void* p) {
    uint a;
    asm("{ .reg .u64 t; cvta.to.shared.u64 t, %1; cvt.u32.u64 %0, t; }" : "=r"(a) : "l"(p));
    return a;
}
__device__ __forceinline__ void cp_async16(uint dst, const void* src) {
    asm volatile("cp.async.cg.shared.global [%0], [%1], 16;" :: "r"(dst), "l"(src));
}
#define CP_COMMIT() asm volatile("cp.async.commit_group;" ::: "memory")
#define CP_WAIT(n)  asm volatile("cp.async.wait_group %0;" :: "n"(n) : "memory")

// =====================================================================
// Kernel 0: E = Wbs @ Butterfly @ Wcr   (64x64)
// =====================================================================
__global__ __launch_bounds__(256) void compute_E_kernel(const float* __restrict__ A_factors,
                                                        const float* __restrict__ Wbs,
                                                        const float* __restrict__ Wcr) {
    extern __shared__ float esm[];
    float* Wcr_s = esm;
    float* G     = esm + N_STATE * RANK;
    __shared__ float Af[LEVELS * 4];
    const int tid = threadIdx.x;
    const int r0 = blockIdx.x * E_ROWS;
    if (tid < LEVELS * 4) Af[tid] = A_factors[tid];

    for (int i = tid; i < N_STATE * RANK / 4; i += 256)
        ((float4*)Wcr_s)[i] = ((const float4*)Wcr)[i];
    for (int i = tid; i < E_ROWS * N_STATE / 4; i += 256)
        ((float4*)G)[i] = ((const float4*)(Wbs + (size_t)r0 * N_STATE))[i];
    __syncthreads();

#pragma unroll
    for (int lvl = 0; lvl < LEVELS; lvl++) {
        const int stride = 128 >> lvl;
        const float a00 = Af[lvl * 4 + 0], a01 = Af[lvl * 4 + 1];
        const float a10 = Af[lvl * 4 + 2], a11 = Af[lvl * 4 + 3];
#pragma unroll
        for (int p = tid; p < E_ROWS * 128; p += 256) {
            int r  = p >> 7;
            int pi = p & 127;
            int low = pi & (stride - 1);
            int n0  = ((pi - low) << 1) | low;
            int n1  = n0 + stride;
            float x0 = G[r * N_STATE + n0];
            float x1 = G[r * N_STATE + n1];
            G[r * N_STATE + n0] = x0 * a00 + x1 * a10;
            G[r * N_STATE + n1] = x0 * a01 + x1 * a11;
        }
        __syncthreads();
    }

    for (int o = tid; o < E_ROWS * RANK; o += 256) {
        int r = o >> 6, j = o & 63;
        float acc = 0.f;
#pragma unroll 8
        for (int n = 0; n < N_STATE; n++)
            acc += G[r * N_STATE + n] * Wcr_s[n * RANK + j];
        g_E[(r0 + r) * RANK + j] = acc;
    }
}

// =====================================================================
// Kernel 1: F1t[n][kw] = hi/lo split of (Wbr @ E)^T. (conflict-free)
// =====================================================================
__global__ __launch_bounds__(256) void compute_F1t_kernel(const float* __restrict__ Wbr) {
    __shared__ float Wst[64 * 65];   // [r][k_local]
    __shared__ float Es[64 * 64];
    __shared__ float Fs[64 * 65];    // [n][k_local]
    const int tid = threadIdx.x;
    const int k0 = blockIdx.x * 64;

#pragma unroll
    for (int i = 0; i < 16; i++) {
        int idx = tid + i * 256;
        int k = idx >> 6, r = idx & 63;
        Wst[r * 65 + k] = Wbr[(size_t)(k0 + k) * 64 + r];
    }
#pragma unroll
    for (int i = 0; i < 4; i++)
        ((float4*)Es)[tid + i * 256] = ((const float4*)g_E)[tid + i * 256];
    __syncthreads();

    const int k = tid & 63, nq = tid >> 6;
#pragma unroll
    for (int nn = 0; nn < 16; nn++) {
        int n = nq * 16 + nn;
        float acc = 0.f;
#pragma unroll 8
        for (int r = 0; r < 64; r++)
            acc += Wst[r * 65 + k] * Es[r * 64 + n];
        Fs[n * 65 + k] = acc;
    }
    __syncthreads();

#pragma unroll
    for (int i = 0; i < 8; i++) {
        int idx = tid + i * 256;
        int n = idx >> 5, kw = idx & 31;
        g_F1t[(size_t)n * (D_MODEL / 2) + blockIdx.x * 32 + kw] =
            split2(Fs[n * 65 + 2 * kw], Fs[n * 65 + 2 * kw + 1]);
    }
}

// =====================================================================
// Kernel 1b: Wt[n][kw] = hi/lo split of Wcm^T.
// =====================================================================
__global__ __launch_bounds__(256) void compute_Wcmt_kernel(const float* __restrict__ Wcm) {
    __shared__ float S[64 * 65];
    const int tid = threadIdx.x;
    const int n0 = blockIdx.x * 64;
#pragma unroll
    for (int it = 0; it < 16; it++) {
        int idx = it * 256 + tid;
        int k = idx >> 6, nn = idx & 63;
        S[nn * 65 + k] = Wcm[(size_t)k * D_MODEL + n0 + nn];
    }
    __syncthreads();
#pragma unroll
    for (int it = 0; it < 8; it++) {
        int idx = it * 256 + tid;
        int nn = idx >> 5, kw = idx & 31;
        g_Wt[(size_t)(n0 + nn) * 32 + kw] = split2(S[nn * 65 + 2 * kw], S[nn * 65 + 2 * kw + 1]);
    }
}

// =====================================================================
// Kernel 2: GEMM1: t = u @ F1.  M=64/CTA, K=2048 (32 chunks of 64).
// 3-stage cp.async pipeline staging BOTH u (fp32) and F1t (ull) in smem.
// =====================================================================
__global__ __launch_bounds__(256) void gemm1_mma(const float* __restrict__ u) {
    extern __shared__ char dsm[];
    const int tid = threadIdx.x;
    const int lane = tid & 31;
    const int w = tid >> 5;
    const int g = lane >> 2, c = lane & 3;
    const int m0 = (w & 3) * 16;
    const int n0 = (w >> 2) * 32;
    const size_t row0 = (size_t)blockIdx.x * 64;

    const uint sbase = smem_u32(dsm);
    const int lr = tid >> 4, lseg = tid & 15;   // staging: row, 16B-segment

    float acc[4][4];
#pragma unroll
    for (int i = 0; i < 4; i++)
#pragma unroll
        for (int j = 0; j < 4; j++) acc[i][j] = 0.f;

    // issue one chunk's loads into stage s
    auto issue = [&](int ch, int s) {
        const uint ub = sbase + (uint)s * STAGE_B;
        const uint bb = ub + U_STAGE_B;
        const float* usrc = u + (row0 + lr) * D_MODEL + ch * 64 + lseg * 4;
        const ull* bsrc = g_F1t + (size_t)lr * (D_MODEL / 2) + ch * 32 + lseg * 2;
#pragma unroll
        for (int j = 0; j < 4; j++) {
            cp_async16(ub + (uint)((lr + j * 16) * UST * 4 + lseg * 16),
                       usrc + (size_t)(j * 16) * D_MODEL);
            cp_async16(bb + (uint)((lr + j * 16) * RSB * 8 + lseg * 16),
                       bsrc + (size_t)(j * 16) * (D_MODEL / 2));
        }
        CP_COMMIT();
    };

    issue(0, 0);
    issue(1, 1);

    for (int ch = 0; ch < 32; ch++) {
        CP_WAIT(NSTAGE - 2);
        __syncthreads();
        if (ch + NSTAGE - 1 < 32) issue(ch + NSTAGE - 1, (ch + NSTAGE - 1) % NSTAGE);

        const float* Us = (const float*)(dsm + (ch % NSTAGE) * STAGE_B);
        const ull* Bs = (const ull*)(dsm + (ch % NSTAGE) * STAGE_B + U_STAGE_B);

#pragma unroll
        for (int ks = 0; ks < 4; ks++) {
            // A fragments from smem fp32 + in-reg hi/lo split
            float2 f0 = *(const float2*)&Us[(m0 + g) * UST + ks * 16 + c * 2];
            float2 f1 = *(const float2*)&Us[(m0 + g + 8) * UST + ks * 16 + c * 2];
            float2 f2 = *(const float2*)&Us[(m0 + g) * UST + ks * 16 + 8 + c * 2];
            float2 f3 = *(const float2*)&Us[(m0 + g + 8) * UST + ks * 16 + 8 + c * 2];
            ull A0 = split2(f0.x, f0.y), A1 = split2(f1.x, f1.y);
            ull A2 = split2(f2.x, f2.y), A3 = split2(f3.x, f3.y);
            uint ah0 = (uint)A0, al0 = (uint)(A0 >> 32);
            uint ah1 = (uint)A1, al1 = (uint)(A1 >> 32);
            uint ah2 = (uint)A2, al2 = (uint)(A2 >> 32);
            uint ah3 = (uint)A3, al3 = (uint)(A3 >> 32);
            ull b0[4], b1[4];
#pragma unroll
            for (int nt = 0; nt < 4; nt++) {
                b0[nt] = Bs[(n0 + nt * 8 + g) * RSB + ks * 8 + c];
                b1[nt] = Bs[(n0 + nt * 8 + g) * RSB + ks * 8 + 4 + c];
            }
#pragma unroll
            for (int nt = 0; nt < 4; nt++)
                mma16816(acc[nt], ah0, ah1, ah2, ah3, (uint)b0[nt], (uint)b1[nt]);
#pragma unroll
            for (int nt = 0; nt < 4; nt++)
                mma16816(acc[nt], ah0, ah1, ah2, ah3,
                         (uint)(b0[nt] >> 32), (uint)(b1[nt] >> 32));
#pragma unroll
            for (int nt = 0; nt < 4; nt++)
                mma16816(acc[nt], al0, al1, al2, al3, (uint)b0[nt], (uint)b1[nt]);
        }
        __syncthreads();   // done reading stage ch before it is overwritten
    }

    // epilogue: t as hi/lo bf16 word pairs (fragment-compatible layout)
#pragma unroll
    for (int nt = 0; nt < 4; nt++) {
        int kw = (n0 >> 1) + nt * 4 + c;
        size_t r = row0 + m0 + g;
        g_t[r * 32 + kw]       = split2(acc[nt][0], acc[nt][1]);
        g_t[(r + 8) * 32 + kw] = split2(acc[nt][2], acc[nt][3]);
    }
}

// =====================================================================
// Kernel 3: GEMM2: out = t @ Wcm + D*u.  Tile 64x128, grid 4096.
// Single cp.async burst stages A(g_t) + B(g_Wt); MMA from smem;
// Dsm-overlay coalesced epilogue.
// =====================================================================
__global__ __launch_bounds__(256) void gemm2_mma(const float* __restrict__ u,
                                                 const float* __restrict__ Dv,
                                                 float* __restrict__ out) {
    extern __shared__ char dsm[];
    ull* Asm = (ull*)dsm;                    // [64 * RSB]
    ull* Bsm = (ull*)(dsm + G2A_B);          // [128 * RSB]
    float* Dsm = (float*)dsm;                // [64][132] overlay after compute

    const int tid = threadIdx.x;
    const int lane = tid & 31;
    const int w = tid >> 5;
    const int g = lane >> 2, c = lane & 3;
    const int m0 = (w & 3) * 16;
    const int n0b = (w >> 2) * 64;
    const int ct = blockIdx.x & 15;
    const int rt = blockIdx.x >> 4;
    const size_t row0 = (size_t)rt * 64;
    const int col0 = ct * 128;

    // stage A + B via cp.async
    {
        const uint ab = smem_u32(Asm);
        const uint bb = smem_u32(Bsm);
        const int lr = tid >> 4, lseg = tid & 15;
#pragma unroll
        for (int j = 0; j < 4; j++) {
            int r = lr + j * 16;
            cp_async16(ab + (uint)(r * RSB * 8 + lseg * 16),
                       g_t + (row0 + r) * 32 + lseg * 2);
        }
#pragma unroll
        for (int j = 0; j < 8; j++) {
            int n = lr + j * 16;
            cp_async16(bb + (uint)(n * RSB * 8 + lseg * 16),
                       g_Wt + (size_t)(col0 + n) * 32 + lseg * 2);
        }
        CP_COMMIT();
        CP_WAIT(0);
        __syncthreads();
    }

    // A fragments
    ull afr[16];
#pragma unroll
    for (int ks = 0; ks < 4; ks++) {
        afr[ks * 4 + 0] = Asm[(m0 + g) * RSB + ks * 8 + c];
        afr[ks * 4 + 1] = Asm[(m0 + g + 8) * RSB + ks * 8 + c];
        afr[ks * 4 + 2] = Asm[(m0 + g) * RSB + ks * 8 + 4 + c];
        afr[ks * 4 + 3] = Asm[(m0 + g + 8) * RSB + ks * 8 + 4 + c];
    }

    float acc[8][4];
#pragma unroll
    for (int i = 0; i < 8; i++)
#pragma unroll
        for (int j = 0; j < 4; j++) acc[i][j] = 0.f;

#pragma unroll
    for (int ks = 0; ks < 4; ks++) {
        uint ah0 = (uint)afr[ks * 4 + 0], al0 = (uint)(afr[ks * 4 + 0] >> 32);
        uint ah1 = (uint)afr[ks * 4 + 1], al1 = (uint)(afr[ks * 4 + 1] >> 32);
        uint ah2 = (uint)afr[ks * 4 + 2], al2 = (uint)(afr[ks * 4 + 2] >> 32);
        uint ah3 = (uint)afr[ks * 4 + 3], al3 = (uint)(afr[ks * 4 + 3] >> 32);
        ull b0[8], b1[8];
#pragma unroll
        for (int nt = 0; nt < 8; nt++) {
            b0[nt] = Bsm[(n0b + nt * 8 + g) * RSB + ks * 8 + c];
            b1[nt] = Bsm[(n0b + nt * 8 + g) * RSB + ks * 8 + 4 + c];
        }
#pragma unroll
        for (int nt = 0; nt < 8; nt++)
            mma16816(acc[nt], ah0, ah1, ah2, ah3, (uint)b0[nt], (uint)b1[nt]);
#pragma unroll
        for (int nt = 0; nt < 8; nt++)
            mma16816(acc[nt], ah0, ah1, ah2, ah3,
                     (uint)(b0[nt] >> 32), (uint)(b1[nt] >> 32));
#pragma unroll
        for (int nt = 0; nt < 8; nt++)
            mma16816(acc[nt], al0, al1, al2, al3, (uint)b0[nt], (uint)b1[nt]);
    }
    __syncthreads();   // tiles consumed; Dsm may overlay

    // stage accumulators into Dsm
#pragma unroll
    for (int nt = 0; nt < 8; nt++) {
        int cc = n0b + nt * 8 + c * 2;
        *(float2*)&Dsm[(m0 + g) * 132 + cc]     = make_float2(acc[nt][0], acc[nt][1]);
        *(float2*)&Dsm[(m0 + g + 8) * 132 + cc] = make_float2(acc[nt][2], acc[nt][3]);
    }
    __syncthreads();

    // coalesced epilogue: out = Dsm + D*u
#pragma unroll
    for (int it = 0; it < 8; it++) {
        int idx = it * 256 + tid;
        int r = idx >> 5, c4 = idx & 31;
        size_t grow = row0 + r;
        int gcol = col0 + c4 * 4;
        float4 dv = *(const float4*)(Dv + gcol);
        float4 uv = *(const float4*)(u + grow * D_MODEL + gcol);
        float4 o;
        o.x = Dsm[r * 132 + c4 * 4 + 0] + dv.x * uv.x;
        o.y = Dsm[r * 132 + c4 * 4 + 1] + dv.y * uv.y;
        o.z = Dsm[r * 132 + c4 * 4 + 2] + dv.z * uv.z;
        o.w = Dsm[r * 132 + c4 * 4 + 3] + dv.w * uv.w;
        *(float4*)(out + grow * D_MODEL + gcol) = o;
    }
}

extern "C" void kernel_launch(void* const* d_in, const int* in_sizes, int n_in,
                              void* d_out, int out_size) {
    const float* u   = (const float*)d_in[0];
    const float* Af  = (const float*)d_in[1];
    const float* Wbr = (const float*)d_in[2];
    const float* Wbs = (const float*)d_in[3];
    const float* Wcr = (const float*)d_in[4];
    const float* Wcm = (const float*)d_in[5];
    const float* Dv  = (const float*)d_in[6];
    float* out = (float*)d_out;

    const int T = in_sizes[0] / D_MODEL;   // 16384

    cudaFuncSetAttribute(compute_E_kernel, cudaFuncAttributeMaxDynamicSharedMemorySize, E_SMEM);
    cudaFuncSetAttribute(gemm1_mma, cudaFuncAttributeMaxDynamicSharedMemorySize, G1_SMEM);
    cudaFuncSetAttribute(gemm2_mma, cudaFuncAttributeMaxDynamicSharedMemorySize, G2_SMEM);

    compute_E_kernel<<<E_CTAS, 256, E_SMEM>>>(Af, Wbs, Wcr);
    compute_F1t_kernel<<<32, 256>>>(Wbr);
    compute_Wcmt_kernel<<<32, 256>>>(Wcm);
    gemm1_mma<<<T / 64, 256, G1_SMEM>>>(u);
    gemm2_mma<<<(T / 64) * (D_MODEL / 128), 256, G2_SMEM>>>(u, Dv, out);
}